// round 1
// baseline (speedup 1.0000x reference)
#include <cuda_runtime.h>
#include <mma.h>

using namespace nvcuda;

#define DIN   4096
#define DOUT  4096
#define NTOK  8192
#define TIDV  4
#define RNK   8
#define NPE   5
#define NCOLS 35      // 3 logits + 32 z columns
#define NPAD  48      // padded to 3 wmma n-tiles
#define CCOLS 32

// Scratch (no allocations allowed): packed M^T and gated coefficients C
__device__ float g_MT[NPAD * DIN];      // [48][4096]
__device__ float g_C[NTOK * CCOLS];     // [8192][32]

// ---------------------------------------------------------------------------
// Kernel 0: pack M^T[n][k]:
//   n<3        : routing col n of lora_route[tid-1][:, n]
//   3<=n<35    : q=n-3, expert j=q/8, rank r=q%8 -> lora_down[j][k][r]
//   n>=35      : 0
// ---------------------------------------------------------------------------
__global__ void pack_mt_kernel(const float* __restrict__ lora_down,
                               const float* __restrict__ lora_route) {
    int idx = blockIdx.x * blockDim.x + threadIdx.x;
    if (idx >= NPAD * DIN) return;
    int n = idx / DIN;
    int k = idx - n * DIN;
    float v = 0.f;
    if (n < 3) {
        v = lora_route[(TIDV - 1) * DIN * NPE + k * NPE + n];
    } else if (n < NCOLS) {
        int q = n - 3;
        v = lora_down[(q >> 3) * (DIN * RNK) + k * RNK + (q & 7)];
    }
    g_MT[n * DIN + k] = v;
}

// ---------------------------------------------------------------------------
// Kernel 1: prep GEMM  Z = x @ M  (tf32 wmma), fused softmax + gating -> g_C
//   grid: NTOK/64 blocks, 128 threads (4 warps), each warp owns 16 rows
// ---------------------------------------------------------------------------
#define P_BM  64
#define P_BK  32
#define P_LDA 40
#define P_LDZ 48

__global__ __launch_bounds__(128) void prep_gemm_kernel(const float* __restrict__ x) {
    __shared__ float As[P_BM][P_LDA];
    __shared__ float Bs[NPAD][P_LDA];
    __shared__ float Zs[P_BM][P_LDZ];
    __shared__ float Om[P_BM][3];

    const int tid  = threadIdx.x;
    const int warp = tid >> 5;
    const int m0   = blockIdx.x * P_BM;
    const int row  = tid >> 1;      // 0..63
    const int half = tid & 1;

    wmma::fragment<wmma::accumulator, 16, 16, 8, float> acc[3];
#pragma unroll
    for (int j = 0; j < 3; j++) wmma::fill_fragment(acc[j], 0.f);

    for (int k0 = 0; k0 < DIN; k0 += P_BK) {
        // A tile: 64 x 32 (2 threads per row, 16 floats each)
#pragma unroll
        for (int v = 0; v < 4; v++) {
            float4 t = *(const float4*)(x + (size_t)(m0 + row) * DIN + k0 + half * 16 + v * 4);
            *(float4*)(&As[row][half * 16 + v * 4]) = t;
        }
        // B tile: 48 x 32 from packed M^T (row-per-n, contiguous along k)
        for (int idx = tid; idx < NPAD * 8; idx += 128) {
            int n = idx >> 3, q = idx & 7;
            float4 t = *(const float4*)(g_MT + n * DIN + k0 + q * 4);
            *(float4*)(&Bs[n][q * 4]) = t;
        }
        __syncthreads();

#pragma unroll
        for (int ks = 0; ks < 4; ks++) {
            const int k = ks * 8;
            wmma::fragment<wmma::matrix_a, 16, 16, 8, wmma::precision::tf32, wmma::row_major> a;
            wmma::load_matrix_sync(a, &As[warp * 16][k], P_LDA);
#pragma unroll
            for (int e = 0; e < a.num_elements; e++) a.x[e] = wmma::__float_to_tf32(a.x[e]);
#pragma unroll
            for (int j = 0; j < 3; j++) {
                wmma::fragment<wmma::matrix_b, 16, 16, 8, wmma::precision::tf32, wmma::col_major> b;
                wmma::load_matrix_sync(b, &Bs[j * 16][k], P_LDA);
#pragma unroll
                for (int e = 0; e < b.num_elements; e++) b.x[e] = wmma::__float_to_tf32(b.x[e]);
                wmma::mma_sync(acc[j], a, b, acc[j]);
            }
        }
        __syncthreads();
    }

#pragma unroll
    for (int j = 0; j < 3; j++)
        wmma::store_matrix_sync(&Zs[warp * 16][j * 16], acc[j], P_LDZ, wmma::mem_row_major);
    __syncthreads();

    if (tid < P_BM) {
        float l0 = Zs[tid][0], l1 = Zs[tid][1], l2 = Zs[tid][2];
        float mx = fmaxf(l0, fmaxf(l1, l2));
        float e0 = expf(l0 - mx), e1 = expf(l1 - mx), e2 = expf(l2 - mx);
        float inv = 1.f / (e0 + e1 + e2);
        Om[tid][0] = e0 * inv; Om[tid][1] = e1 * inv; Om[tid][2] = e2 * inv;
    }
    __syncthreads();

    for (int idx = tid; idx < P_BM * CCOLS; idx += 128) {
        int m = idx >> 5, q = idx & 31;
        float w = (q < 24) ? Om[m][q >> 3] : 1.f;
        g_C[(size_t)(m0 + m) * CCOLS + q] = Zs[m][3 + q] * w;
    }
}

// ---------------------------------------------------------------------------
// Kernel 2: fused main GEMM  out = x @ W^T + C @ U  (tf32 wmma)
//   BM=BN=128, BK=32, 256 threads = 8 warps (2x4), warp tile 64x32
//   double-buffered smem (ld=40 keeps all float4 stores 16B-aligned),
//   delta handled as one extra K-tile (K=32) from g_C / lora_up.
// ---------------------------------------------------------------------------
#define BM   128
#define BN   128
#define BK   32
#define MLDS 40
#define NKT  (DIN / BK)   // 128

__global__ __launch_bounds__(256, 2) void main_gemm_kernel(
    const float* __restrict__ x,
    const float* __restrict__ W,
    const float* __restrict__ lora_up,
    float* __restrict__ out)
{
    extern __shared__ float sm[];
    float (*As)[BM][MLDS] = (float (*)[BM][MLDS])sm;
    float (*Bs)[BN][MLDS] = (float (*)[BN][MLDS])(sm + 2 * BM * MLDS);

    const int tid  = threadIdx.x;
    const int warp = tid >> 5;
    const int wm   = warp >> 2;   // 0..1
    const int wn   = warp & 3;    // 0..3
    const int m0   = blockIdx.y * BM;
    const int n0   = blockIdx.x * BN;
    const int row  = tid >> 1;    // 0..127
    const int half = tid & 1;

    wmma::fragment<wmma::accumulator, 16, 16, 8, float> acc[4][2];
#pragma unroll
    for (int i = 0; i < 4; i++)
#pragma unroll
        for (int j = 0; j < 2; j++) wmma::fill_fragment(acc[i][j], 0.f);

    const float* aptr = x + (size_t)(m0 + row) * DIN + half * 16;
    const float* bptr = W + (size_t)(n0 + row) * DIN + half * 16;

    float4 ra[4], rb[4];
#pragma unroll
    for (int v = 0; v < 4; v++) {
        ra[v] = *(const float4*)(aptr + v * 4);
        rb[v] = *(const float4*)(bptr + v * 4);
    }
#pragma unroll
    for (int v = 0; v < 4; v++) {
        *(float4*)(&As[0][row][half * 16 + v * 4]) = ra[v];
        *(float4*)(&Bs[0][row][half * 16 + v * 4]) = rb[v];
    }
    __syncthreads();

    for (int kt = 0; kt < NKT; kt++) {
        const int cur = kt & 1;
        if (kt + 1 < NKT) {
            const float* ap = aptr + (kt + 1) * BK;
            const float* bp = bptr + (kt + 1) * BK;
#pragma unroll
            for (int v = 0; v < 4; v++) {
                ra[v] = *(const float4*)(ap + v * 4);
                rb[v] = *(const float4*)(bp + v * 4);
            }
        }
#pragma unroll
        for (int ks = 0; ks < 4; ks++) {
            const int k = ks * 8;
            wmma::fragment<wmma::matrix_a, 16, 16, 8, wmma::precision::tf32, wmma::row_major> a[4];
            wmma::fragment<wmma::matrix_b, 16, 16, 8, wmma::precision::tf32, wmma::col_major> b[2];
#pragma unroll
            for (int i = 0; i < 4; i++) {
                wmma::load_matrix_sync(a[i], &As[cur][wm * 64 + i * 16][k], MLDS);
#pragma unroll
                for (int e = 0; e < a[i].num_elements; e++) a[i].x[e] = wmma::__float_to_tf32(a[i].x[e]);
            }
#pragma unroll
            for (int j = 0; j < 2; j++) {
                wmma::load_matrix_sync(b[j], &Bs[cur][wn * 32 + j * 16][k], MLDS);
#pragma unroll
                for (int e = 0; e < b[j].num_elements; e++) b[j].x[e] = wmma::__float_to_tf32(b[j].x[e]);
            }
#pragma unroll
            for (int i = 0; i < 4; i++)
#pragma unroll
                for (int j = 0; j < 2; j++)
                    wmma::mma_sync(acc[i][j], a[i], b[j], acc[i][j]);
        }
        if (kt + 1 < NKT) {
            const int nxt = cur ^ 1;
#pragma unroll
            for (int v = 0; v < 4; v++) {
                *(float4*)(&As[nxt][row][half * 16 + v * 4]) = ra[v];
                *(float4*)(&Bs[nxt][row][half * 16 + v * 4]) = rb[v];
            }
            __syncthreads();
        }
    }

    // Extra K-tile: delta = C[128,32] @ U[32,128]  (U = first 32 rows of lora_up)
    __syncthreads();
#pragma unroll
    for (int v = 0; v < 4; v++) {
        float4 t = *(const float4*)(g_C + (size_t)(m0 + row) * CCOLS + half * 16 + v * 4);
        *(float4*)(&As[0][row][half * 16 + v * 4]) = t;
    }
    for (int idx = tid; idx < BN * BK; idx += 256) {
        int n = idx & 127, k = idx >> 7;
        Bs[0][n][k] = lora_up[(size_t)k * DOUT + n0 + n];
    }
    __syncthreads();

#pragma unroll
    for (int ks = 0; ks < 4; ks++) {
        const int k = ks * 8;
        wmma::fragment<wmma::matrix_a, 16, 16, 8, wmma::precision::tf32, wmma::row_major> a[4];
        wmma::fragment<wmma::matrix_b, 16, 16, 8, wmma::precision::tf32, wmma::col_major> b[2];
#pragma unroll
        for (int i = 0; i < 4; i++) {
            wmma::load_matrix_sync(a[i], &As[0][wm * 64 + i * 16][k], MLDS);
#pragma unroll
            for (int e = 0; e < a[i].num_elements; e++) a[i].x[e] = wmma::__float_to_tf32(a[i].x[e]);
        }
#pragma unroll
        for (int j = 0; j < 2; j++) {
            wmma::load_matrix_sync(b[j], &Bs[0][wn * 32 + j * 16][k], MLDS);
#pragma unroll
            for (int e = 0; e < b[j].num_elements; e++) b[j].x[e] = wmma::__float_to_tf32(b[j].x[e]);
        }
#pragma unroll
        for (int i = 0; i < 4; i++)
#pragma unroll
            for (int j = 0; j < 2; j++)
                wmma::mma_sync(acc[i][j], a[i], b[j], acc[i][j]);
    }

#pragma unroll
    for (int i = 0; i < 4; i++)
#pragma unroll
        for (int j = 0; j < 2; j++)
            wmma::store_matrix_sync(out + (size_t)(m0 + wm * 64 + i * 16) * DOUT + n0 + wn * 32 + j * 16,
                                    acc[i][j], DOUT, wmma::mem_row_major);
}

// ---------------------------------------------------------------------------
// Launch
// ---------------------------------------------------------------------------
extern "C" void kernel_launch(void* const* d_in, const int* in_sizes, int n_in,
                              void* d_out, int out_size) {
    const float* x          = (const float*)d_in[0];
    const float* W          = (const float*)d_in[1];
    const float* lora_down  = (const float*)d_in[2];
    const float* lora_up    = (const float*)d_in[3];
    const float* lora_route = (const float*)d_in[4];
    float* out = (float*)d_out;

    const size_t main_smem = (size_t)4 * BM * MLDS * sizeof(float);  // 81920 B
    cudaFuncSetAttribute(main_gemm_kernel, cudaFuncAttributeMaxDynamicSharedMemorySize,
                         (int)main_smem);

    pack_mt_kernel<<<(NPAD * DIN + 255) / 256, 256>>>(lora_down, lora_route);
    prep_gemm_kernel<<<NTOK / P_BM, 128>>>(x);
    dim3 grid(DOUT / BN, NTOK / BM);
    main_gemm_kernel<<<grid, 256, main_smem>>>(x, W, lora_up, out);
}

// round 3
// speedup vs baseline: 3.0080x; 3.0080x over previous
#include <cuda_runtime.h>
#include <cstdint>
#include <mma.h>

using namespace nvcuda;

#define DIN   4096
#define DOUT  4096
#define NTOK  8192
#define TIDV  4
#define RNK   8
#define NPE   5
#define NCOLS 35
#define NPAD  48
#define CCOLS 32

__device__ float g_MT[NPAD * DIN];
__device__ float g_C[NTOK * CCOLS];

// ===========================================================================
// helpers
// ===========================================================================
__device__ __forceinline__ uint32_t smem_u32(const void* p) {
    uint32_t r;
    asm("{ .reg .u64 t; cvta.to.shared.u64 t, %1; cvt.u32.u64 %0, t; }" : "=r"(r) : "l"(p));
    return r;
}

__device__ __forceinline__ void cp16(uint32_t dst, const void* src) {
    asm volatile("cp.async.cg.shared.global [%0], [%1], 16;" :: "r"(dst), "l"(src));
}

__device__ __forceinline__ uint32_t f2tf(float f) {
    uint32_t u;
    asm("cvt.rna.tf32.f32 %0, %1;" : "=r"(u) : "f"(f));
    return u;
}

__device__ __forceinline__ void mma_1688(float* d, const uint32_t* a, const uint32_t* b) {
    asm volatile(
        "mma.sync.aligned.m16n8k8.row.col.f32.tf32.tf32.f32 "
        "{%0,%1,%2,%3}, {%4,%5,%6,%7}, {%8,%9}, {%0,%1,%2,%3};"
        : "+f"(d[0]), "+f"(d[1]), "+f"(d[2]), "+f"(d[3])
        : "r"(a[0]), "r"(a[1]), "r"(a[2]), "r"(a[3]), "r"(b[0]), "r"(b[1]));
}

// ===========================================================================
// Kernel 0: pack M^T (routing cols + down-proj cols)   [unchanged, passing]
// ===========================================================================
__global__ void pack_mt_kernel(const float* __restrict__ lora_down,
                               const float* __restrict__ lora_route) {
    int idx = blockIdx.x * blockDim.x + threadIdx.x;
    if (idx >= NPAD * DIN) return;
    int n = idx / DIN;
    int k = idx - n * DIN;
    float v = 0.f;
    if (n < 3) {
        v = lora_route[(TIDV - 1) * DIN * NPE + k * NPE + n];
    } else if (n < NCOLS) {
        int q = n - 3;
        v = lora_down[(q >> 3) * (DIN * RNK) + k * RNK + (q & 7)];
    }
    g_MT[n * DIN + k] = v;
}

// ===========================================================================
// Kernel 1: prep GEMM Z = x @ M + softmax gating -> g_C  [unchanged, passing]
// ===========================================================================
#define P_BM  64
#define P_BK  32
#define P_LDA 40
#define P_LDZ 48

__global__ __launch_bounds__(128) void prep_gemm_kernel(const float* __restrict__ x) {
    __shared__ float As[P_BM][P_LDA];
    __shared__ float Bs[NPAD][P_LDA];
    __shared__ float Zs[P_BM][P_LDZ];
    __shared__ float Om[P_BM][3];

    const int tid  = threadIdx.x;
    const int warp = tid >> 5;
    const int m0   = blockIdx.x * P_BM;
    const int row  = tid >> 1;
    const int half = tid & 1;

    wmma::fragment<wmma::accumulator, 16, 16, 8, float> acc[3];
#pragma unroll
    for (int j = 0; j < 3; j++) wmma::fill_fragment(acc[j], 0.f);

    for (int k0 = 0; k0 < DIN; k0 += P_BK) {
#pragma unroll
        for (int v = 0; v < 4; v++) {
            float4 t = *(const float4*)(x + (size_t)(m0 + row) * DIN + k0 + half * 16 + v * 4);
            *(float4*)(&As[row][half * 16 + v * 4]) = t;
        }
        for (int idx = tid; idx < NPAD * 8; idx += 128) {
            int n = idx >> 3, q = idx & 7;
            float4 t = *(const float4*)(g_MT + n * DIN + k0 + q * 4);
            *(float4*)(&Bs[n][q * 4]) = t;
        }
        __syncthreads();

#pragma unroll
        for (int ks = 0; ks < 4; ks++) {
            const int k = ks * 8;
            wmma::fragment<wmma::matrix_a, 16, 16, 8, wmma::precision::tf32, wmma::row_major> a;
            wmma::load_matrix_sync(a, &As[warp * 16][k], P_LDA);
#pragma unroll
            for (int e = 0; e < a.num_elements; e++) a.x[e] = wmma::__float_to_tf32(a.x[e]);
#pragma unroll
            for (int j = 0; j < 3; j++) {
                wmma::fragment<wmma::matrix_b, 16, 16, 8, wmma::precision::tf32, wmma::col_major> b;
                wmma::load_matrix_sync(b, &Bs[j * 16][k], P_LDA);
#pragma unroll
                for (int e = 0; e < b.num_elements; e++) b.x[e] = wmma::__float_to_tf32(b.x[e]);
                wmma::mma_sync(acc[j], a, b, acc[j]);
            }
        }
        __syncthreads();
    }

#pragma unroll
    for (int j = 0; j < 3; j++)
        wmma::store_matrix_sync(&Zs[warp * 16][j * 16], acc[j], P_LDZ, wmma::mem_row_major);
    __syncthreads();

    if (tid < P_BM) {
        float l0 = Zs[tid][0], l1 = Zs[tid][1], l2 = Zs[tid][2];
        float mx = fmaxf(l0, fmaxf(l1, l2));
        float e0 = expf(l0 - mx), e1 = expf(l1 - mx), e2 = expf(l2 - mx);
        float inv = 1.f / (e0 + e1 + e2);
        Om[tid][0] = e0 * inv; Om[tid][1] = e1 * inv; Om[tid][2] = e2 * inv;
    }
    __syncthreads();

    for (int idx = tid; idx < P_BM * CCOLS; idx += 128) {
        int m = idx >> 5, q = idx & 31;
        float w = (q < 24) ? Om[m][q >> 3] : 1.f;
        g_C[(size_t)(m0 + m) * CCOLS + q] = Zs[m][3 + q] * w;
    }
}

// ===========================================================================
// Kernel 2: main GEMM out = x @ W^T + C @ U  via raw mma.sync tf32
//   block 128x256, 8 warps (2x4), warp tile 64x64 (4 m-tiles x 8 n-tiles)
//   3-stage cp.async pipeline, XOR-swizzled smem, conflict-free LDS.32
// ===========================================================================
#define BM 128
#define BN 256
#define BKF 32
#define NCHUNK (DIN / BKF)        // 128
#define A_FL (BM * BKF)           // 4096 floats
#define B_FL (BN * BKF)           // 8192 floats
#define STG_FL (A_FL + B_FL)      // 12288 floats
#define A_BYTES (A_FL * 4)
#define STG_BYTES (STG_FL * 4)    // 49152
#define SMEM_BYTES (3 * STG_BYTES) // 147456

// compute one 32-wide K chunk from swizzled smem tiles
__device__ __forceinline__ void compute_chunk(
    const float* __restrict__ As, const float* __restrict__ Bs,
    const int* ra0, const int* ra1, const int* rb,
    int qid, float acc[4][8][4])
{
#pragma unroll
    for (int k = 0; k < 4; k++) {
        const int kb = k * 2;
        const int s0 = ((kb ^ qid) << 2);
        const int s1 = (((kb + 1) ^ qid) << 2);
        uint32_t a[4][4];
#pragma unroll
        for (int mi = 0; mi < 4; mi++) {
            a[mi][0] = f2tf(As[ra0[mi] + s0]);
            a[mi][1] = f2tf(As[ra1[mi] + s0]);
            a[mi][2] = f2tf(As[ra0[mi] + s1]);
            a[mi][3] = f2tf(As[ra1[mi] + s1]);
        }
        uint32_t b[8][2];
#pragma unroll
        for (int nj = 0; nj < 8; nj++) {
            b[nj][0] = f2tf(Bs[rb[nj] + s0]);
            b[nj][1] = f2tf(Bs[rb[nj] + s1]);
        }
#pragma unroll
        for (int mi = 0; mi < 4; mi++)
#pragma unroll
            for (int nj = 0; nj < 8; nj++)
                mma_1688(acc[mi][nj], a[mi], b[nj]);
    }
}

__global__ __launch_bounds__(256, 1) void main_mma_kernel(
    const float* __restrict__ x,
    const float* __restrict__ W,
    const float* __restrict__ lora_up,
    float* __restrict__ out)
{
    extern __shared__ float sm[];
    const uint32_t smb = smem_u32(sm);

    const int tid  = threadIdx.x;
    const int warp = tid >> 5;
    const int lane = tid & 31;
    const int qid  = lane >> 2;
    const int tid4 = lane & 3;
    const int wm   = warp >> 2;   // 0..1
    const int wn   = warp & 3;    // 0..3
    const int m0   = blockIdx.y * BM;
    const int n0   = blockIdx.x * BN;

    // fragment base offsets (floats) into swizzled [row][32] tiles
    int ra0[4], ra1[4], rb[8];
#pragma unroll
    for (int mi = 0; mi < 4; mi++) {
        int r = wm * 64 + mi * 16 + qid;
        ra0[mi] = r * 32 + tid4;
        ra1[mi] = ra0[mi] + 8 * 32;
    }
#pragma unroll
    for (int nj = 0; nj < 8; nj++) {
        int r = wn * 64 + nj * 8 + qid;
        rb[nj] = r * 32 + tid4;
    }

    // cp.async src/dst bases: thread handles rows r0 + v*32, 16B block blk
    const int r0  = tid >> 3;
    const int blk = tid & 7;
    const uint32_t aD = (uint32_t)((r0 * 32 + ((blk ^ (r0 & 7)) << 2)) * 4); // byte off
    const float* aS = x + (size_t)(m0 + r0) * DIN + blk * 4;
    const float* bS = W + (size_t)(n0 + r0) * DIN + blk * 4;

    float acc[4][8][4];
#pragma unroll
    for (int mi = 0; mi < 4; mi++)
#pragma unroll
        for (int nj = 0; nj < 8; nj++)
#pragma unroll
            for (int e = 0; e < 4; e++) acc[mi][nj][e] = 0.f;

    // prologue: chunks 0,1 -> stages 0,1
#pragma unroll
    for (int p = 0; p < 2; p++) {
        const uint32_t ab = smb + p * STG_BYTES;
#pragma unroll
        for (int v = 0; v < 4; v++) cp16(ab + aD + v * 4096, aS + (size_t)v * 32 * DIN + p * 32);
#pragma unroll
        for (int v = 0; v < 8; v++) cp16(ab + A_BYTES + aD + v * 4096, bS + (size_t)v * 32 * DIN + p * 32);
        asm volatile("cp.async.commit_group;" ::: "memory");
    }

    int stage = 0;
#pragma unroll 1
    for (int c = 0; c < NCHUNK; c++) {
        if (c == NCHUNK - 1) asm volatile("cp.async.wait_group 0;" ::: "memory");
        else                 asm volatile("cp.async.wait_group 1;" ::: "memory");
        __syncthreads();

        if (c + 2 < NCHUNK) {
            int ns = stage + 2; if (ns >= 3) ns -= 3;
            const uint32_t ab = smb + ns * STG_BYTES;
            const int ko = (c + 2) * 32;
#pragma unroll
            for (int v = 0; v < 4; v++) cp16(ab + aD + v * 4096, aS + (size_t)v * 32 * DIN + ko);
#pragma unroll
            for (int v = 0; v < 8; v++) cp16(ab + A_BYTES + aD + v * 4096, bS + (size_t)v * 32 * DIN + ko);
            asm volatile("cp.async.commit_group;" ::: "memory");
        }

        compute_chunk(sm + stage * STG_FL, sm + stage * STG_FL + A_FL, ra0, ra1, rb, qid, acc);

        stage++; if (stage == 3) stage = 0;
    }

    // ---- LoRA delta chunk: A = gated C [128,32], B[n][k] = lora_up[k][n0+n]
    __syncthreads();
    {
        // A side: same (row, 16B-block) mapping as main A tile
#pragma unroll
        for (int v = 0; v < 4; v++) {
            float4 t = *(const float4*)(g_C + (size_t)(m0 + r0) * CCOLS + blk * 4 + v * 32 * CCOLS);
            *(float4*)((char*)sm + aD + v * 4096) = t;
        }
        // B side: transpose U (32 x BN) into [n][32] swizzled
        const int n = tid;            // 0..255
        const int nx = (n & 7) ;
#pragma unroll
        for (int k = 0; k < 32; k++) {
            sm[A_FL + n * 32 + (((k >> 2) ^ nx) << 2) + (k & 3)] =
                lora_up[(size_t)k * DOUT + n0 + n];
        }
    }
    __syncthreads();
    compute_chunk(sm, sm + A_FL, ra0, ra1, rb, qid, acc);

    // ---- epilogue: D fragment (c0,c1)->(row, col..col+1), (c2,c3)->(row+8)
#pragma unroll
    for (int mi = 0; mi < 4; mi++) {
        const int row = m0 + wm * 64 + mi * 16 + qid;
#pragma unroll
        for (int nj = 0; nj < 8; nj++) {
            const int col = n0 + wn * 64 + nj * 8 + tid4 * 2;
            float2 v0 = make_float2(acc[mi][nj][0], acc[mi][nj][1]);
            float2 v1 = make_float2(acc[mi][nj][2], acc[mi][nj][3]);
            *(float2*)(out + (size_t)row * DOUT + col) = v0;
            *(float2*)(out + (size_t)(row + 8) * DOUT + col) = v1;
        }
    }
}

// ===========================================================================
// Launch
// ===========================================================================
extern "C" void kernel_launch(void* const* d_in, const int* in_sizes, int n_in,
                              void* d_out, int out_size) {
    const float* x          = (const float*)d_in[0];
    const float* W          = (const float*)d_in[1];
    const float* lora_down  = (const float*)d_in[2];
    const float* lora_up    = (const float*)d_in[3];
    const float* lora_route = (const float*)d_in[4];
    float* out = (float*)d_out;

    cudaFuncSetAttribute(main_mma_kernel, cudaFuncAttributeMaxDynamicSharedMemorySize,
                         SMEM_BYTES);

    pack_mt_kernel<<<(NPAD * DIN + 255) / 256, 256>>>(lora_down, lora_route);
    prep_gemm_kernel<<<NTOK / P_BM, 128>>>(x);
    dim3 grid(DOUT / BN, NTOK / BM);   // (16, 64)
    main_mma_kernel<<<grid, 256, SMEM_BYTES>>>(x, W, lora_up, out);
}